// round 13
// baseline (speedup 1.0000x reference)
#include <cuda_runtime.h>

#define BMAX 16384

__device__ float g_y2[BMAX * 400];          // conv2+pool output, flattened (C,H,W)
__device__ unsigned g_w1hi[400 * 128];      // tf32 hi plane, [k][c]
__device__ unsigned g_w1lo[400 * 128];      // tf32 lo plane, [k][c]
__device__ float g_w2T[128 * 64];           // fc2_w packed [k/4][c][4]

__device__ __forceinline__ float4 fma4(float4 a, float4 b, float4 c) {
    return make_float4(fmaf(a.x, b.x, c.x), fmaf(a.y, b.y, c.y),
                       fmaf(a.z, b.z, c.z), fmaf(a.w, b.w, c.w));
}
__device__ __forceinline__ unsigned cvt_tf32(float f) {
    unsigned u; asm("cvt.rna.tf32.f32 %0, %1;" : "=r"(u) : "f"(f)); return u;
}
__device__ __forceinline__ void mma_tf32(float& d0, float& d1, float& d2, float& d3,
                                         unsigned a0, unsigned a1, unsigned a2, unsigned a3,
                                         unsigned b0, unsigned b1) {
    asm("mma.sync.aligned.m16n8k8.row.col.f32.tf32.tf32.f32 "
        "{%0,%1,%2,%3}, {%4,%5,%6,%7}, {%8,%9}, {%0,%1,%2,%3};"
        : "+f"(d0), "+f"(d1), "+f"(d2), "+f"(d3)
        : "r"(a0), "r"(a1), "r"(a2), "r"(a3), "r"(b0), "r"(b1));
}

// ---------------------------------------------------------------------------
// Weight prep: W1 -> tf32 hi/lo planes [k][c]; W2 -> packed [k/4][c][4].
// ---------------------------------------------------------------------------
__global__ void __launch_bounds__(256) kT(const float* __restrict__ fc_w,
                                          const float* __restrict__ fc2_w) {
    const int i = blockIdx.x * 256 + threadIdx.x;
    if (i < 51200) {
        const int c = i / 400, k = i - c * 400;
        const float v = fc_w[i];
        const unsigned hi = cvt_tf32(v);
        const float lo = v - __uint_as_float(hi);
        g_w1hi[k * 128 + c] = hi;
        g_w1lo[k * 128 + c] = cvt_tf32(lo);
    }
    if (i < 8192) {
        const int c = i / 128, k = i - c * 128;
        g_w2T[(k >> 2) * 256 + c * 4 + (k & 3)] = fc2_w[i];
    }
}

// ---------------------------------------------------------------------------
// Fused conv kernel, 2 images / 160 threads (exact R7 configuration).
// ---------------------------------------------------------------------------
__global__ void __launch_bounds__(160) k12_conv(const float* __restrict__ x,
                                                const float* __restrict__ w1,
                                                const float* __restrict__ b1,
                                                const float* __restrict__ w2,
                                                const float* __restrict__ b2) {
    __shared__ __align__(16) float SM[8888];
    float*  Tbuf = SM;                   // [2 img][12 y][8 ic][5 p][4] = 3840
    float*  sx   = SM;                   // [2 img][784] (alias, disjoint lifetime)
    float*  sy1  = SM + 3840;            // [2 img][8 ic][13 y][16] = 3328
    float4* suw4 = (float4*)(SM + 7168); // [16 oc][25] float4
    float4* sw14 = (float4*)(SM + 8768); // [8 oc][3 ky] float4 (w0,w1,w2,0)
    float*  sb1  = SM + 8864;
    float*  sb2  = SM + 8872;

    const int img0 = blockIdx.x * 2;
    const int t = threadIdx.x;

    // ---- stage 0 ----
    if (t < 24) {
        const int oc = t / 3, ky = t - oc * 3;
        const float* g = w1 + oc * 9 + ky * 3;
        sw14[t] = make_float4(g[0], g[1], g[2], 0.f);
    }
    if (t >= 80 && t < 88)   sb1[t - 80] = b1[t - 80];
    if (t >= 88 && t < 104)  sb2[t - 88] = b2[t - 88];
    for (int i = t; i < 384; i += 160) {         // Winograd weight transform
        const int oc = i / 24, rem = i - oc * 24;
        const int ic = rem / 3, ky = rem - ic * 3;
        const float* g = w2 + oc * 72 + ic * 9 + ky * 3;
        const float a = g[0], bq = g[1], c = g[2];
        suw4[oc * 25 + ic * 3 + ky] =
            make_float4(a, 0.5f * (a + bq + c), 0.5f * (a - bq + c), c);
    }
    {
        const float4* xs = (const float4*)(x + img0 * 784);
        for (int i = t; i < 392; i += 160) ((float4*)sx)[i] = xs[i];
    }
    __syncthreads();

    // ---- phase A: conv1 + bias + relu + pool -> sy1 ----
    for (int i = t; i < 338; i += 160) {
        const int sub = i / 169;
        const int local = i - sub * 169;
        const int py = local / 13, px = local - py * 13;
        const float* xim = sx + sub * 784 + (2 * py) * 28 + 2 * px;

        float win[4][4];
#pragma unroll
        for (int j = 0; j < 4; j++) {
            const float2* rr = (const float2*)(xim + j * 28);
            const float2 a = rr[0], b = rr[1];
            win[j][0] = a.x; win[j][1] = a.y; win[j][2] = b.x; win[j][3] = b.y;
        }

        float* outp = sy1 + sub * 1664 + py * 16 + px;
#pragma unroll
        for (int oc = 0; oc < 8; oc++) {
            float c00 = 0.f, c01 = 0.f, c10 = 0.f, c11 = 0.f;
#pragma unroll
            for (int ky = 0; ky < 3; ky++) {
                const float4 wv = sw14[oc * 3 + ky];
                c00 = fmaf(win[ky][0], wv.x, c00);
                c00 = fmaf(win[ky][1], wv.y, c00);
                c00 = fmaf(win[ky][2], wv.z, c00);
                c01 = fmaf(win[ky][1], wv.x, c01);
                c01 = fmaf(win[ky][2], wv.y, c01);
                c01 = fmaf(win[ky][3], wv.z, c01);
                c10 = fmaf(win[ky + 1][0], wv.x, c10);
                c10 = fmaf(win[ky + 1][1], wv.y, c10);
                c10 = fmaf(win[ky + 1][2], wv.z, c10);
                c11 = fmaf(win[ky + 1][1], wv.x, c11);
                c11 = fmaf(win[ky + 1][2], wv.y, c11);
                c11 = fmaf(win[ky + 1][3], wv.z, c11);
            }
            const float m = fmaxf(fmaxf(c00, c01), fmaxf(c10, c11)) + sb1[oc];
            outp[oc * 208] = fmaxf(m, 0.f);
        }
    }
    __syncthreads();

    // ---- phase B1: input transform ----
    for (int i = t; i < 192; i += 160) {
        const int img = i / 96, rem = i - img * 96;
        const int y = rem / 8, ic = rem - y * 8;
        const float4* rp = (const float4*)(sy1 + img * 1664 + ic * 208 + y * 16);
        float r[12];
#pragma unroll
        for (int m = 0; m < 3; m++) {
            const float4 v = rp[m];
            r[4 * m] = v.x; r[4 * m + 1] = v.y; r[4 * m + 2] = v.z; r[4 * m + 3] = v.w;
        }
        float4* dst = (float4*)(Tbuf + img * 1920 + (y * 8 + ic) * 20);
#pragma unroll
        for (int p = 0; p < 5; p++)
            dst[p] = make_float4(r[2 * p] - r[2 * p + 2],
                                 r[2 * p + 1] + r[2 * p + 2],
                                 r[2 * p + 2] - r[2 * p + 1],
                                 r[2 * p + 1] - r[2 * p + 3]);
    }
    __syncthreads();

    // ---- phase B2: m-space conv2 + pool + bias + relu ----
    const int sub = t / 80;
    const int r = t - sub * 80;
    const int py = r >> 4, oc = r & 15;
    const float* Timg = Tbuf + sub * 1920;
    const float4* wbase = suw4 + oc * 25;

    float4 macc[2][5];
#pragma unroll
    for (int a = 0; a < 2; a++)
#pragma unroll
        for (int p = 0; p < 5; p++) macc[a][p] = make_float4(0.f, 0.f, 0.f, 0.f);

#pragma unroll 2
    for (int ic = 0; ic < 8; ic++) {
        const float4 u0 = wbase[ic * 3 + 0];
        const float4 u1 = wbase[ic * 3 + 1];
        const float4 u2 = wbase[ic * 3 + 2];
#pragma unroll
        for (int s = 0; s < 4; s++) {
            const float4* Trow = (const float4*)(Timg + ((2 * py + s) * 8 + ic) * 20);
            float4 tr[5];
#pragma unroll
            for (int p = 0; p < 5; p++) tr[p] = Trow[p];
            if (s < 3) {
                const float4 u = (s == 0) ? u0 : (s == 1) ? u1 : u2;
#pragma unroll
                for (int p = 0; p < 5; p++) macc[0][p] = fma4(tr[p], u, macc[0][p]);
            }
            if (s >= 1) {
                const float4 u = (s == 1) ? u0 : (s == 2) ? u1 : u2;
#pragma unroll
                for (int p = 0; p < 5; p++) macc[1][p] = fma4(tr[p], u, macc[1][p]);
            }
        }
    }

    float* outp = g_y2 + (img0 + sub) * 400 + oc * 25 + py * 5;
    const float bb = sb2[oc];
#pragma unroll
    for (int p = 0; p < 5; p++) {
        const float o00 = macc[0][p].x + macc[0][p].y + macc[0][p].z;
        const float o01 = macc[0][p].y - macc[0][p].z - macc[0][p].w;
        const float o10 = macc[1][p].x + macc[1][p].y + macc[1][p].z;
        const float o11 = macc[1][p].y - macc[1][p].z - macc[1][p].w;
        const float m = fmaxf(fmaxf(o00, o01), fmaxf(o10, o11));
        outp[p] = fmaxf(m + bb, 0.f);
    }
}

// ---------------------------------------------------------------------------
// Kernel 3: fc1 via tf32x3 tensor-core MMA (m16n8k8), fc2/fc3 scalar (R7 form).
// 16 rows per block, 128 threads = 4 warps; warp w owns cols [w*32, w*32+32).
// ---------------------------------------------------------------------------
__global__ void __launch_bounds__(128) k3_fc(const float* __restrict__ fc_b,
                                             const float* __restrict__ fc2_b,
                                             const float* __restrict__ fc3_w,
                                             const float* __restrict__ fc3_b,
                                             float* __restrict__ out) {
    __shared__ __align__(16) float sx[16 * 400];
    __shared__ __align__(16) float sh1[16 * 128];
    __shared__ __align__(16) float sh2[16 * 64];
    __shared__ __align__(16) float sw3[640];
    __shared__ float sb3[10];

    const int r0 = blockIdx.x * 16;
    const int t = threadIdx.x;

    {
        const float4* xin = (const float4*)(g_y2 + r0 * 400);
        for (int i = t; i < 1600; i += 128) ((float4*)sx)[i] = xin[i];
        for (int i = t; i < 160; i += 128) ((float4*)sw3)[i] = ((const float4*)fc3_w)[i];
        if (t < 10) sb3[t] = fc3_b[t];
    }
    __syncthreads();

    // ---- stage 1 (tensor cores): h1 = relu(X.W1^T + b1), M=16 N=128 K=400 ----
    {
        const int lane = t & 31, w = t >> 5;
        const int g = lane >> 2;          // groupID 0..7
        const int tig = lane & 3;         // threadID_in_group 0..3

        float acc[4][4];
#pragma unroll
        for (int nt = 0; nt < 4; nt++)
#pragma unroll
            for (int j = 0; j < 4; j++) acc[nt][j] = 0.f;

        const float* ar0 = sx + g * 400 + tig;
        const float* ar1 = sx + (g + 8) * 400 + tig;
        const int nb_g = w * 32 + g;      // B-fragment column for this thread

        for (int kt = 0; kt < 50; kt++) {
            const int k0 = kt * 8;
            // A fragment (rows g, g+8; cols tig, tig+4 of this k-tile)
            const float a0f = ar0[k0],     a1f = ar1[k0];
            const float a2f = ar0[k0 + 4], a3f = ar1[k0 + 4];
            const unsigned a0h = cvt_tf32(a0f), a1h = cvt_tf32(a1f);
            const unsigned a2h = cvt_tf32(a2f), a3h = cvt_tf32(a3f);
            const unsigned a0l = cvt_tf32(a0f - __uint_as_float(a0h));
            const unsigned a1l = cvt_tf32(a1f - __uint_as_float(a1h));
            const unsigned a2l = cvt_tf32(a2f - __uint_as_float(a2h));
            const unsigned a3l = cvt_tf32(a3f - __uint_as_float(a3h));

            const unsigned* bh0 = g_w1hi + (k0 + tig) * 128 + nb_g;
            const unsigned* bh1 = g_w1hi + (k0 + tig + 4) * 128 + nb_g;
            const unsigned* bl0 = g_w1lo + (k0 + tig) * 128 + nb_g;
            const unsigned* bl1 = g_w1lo + (k0 + tig + 4) * 128 + nb_g;
#pragma unroll
            for (int nt = 0; nt < 4; nt++) {
                const unsigned b0h = bh0[nt * 8], b1h = bh1[nt * 8];
                const unsigned b0l = bl0[nt * 8], b1l = bl1[nt * 8];
                mma_tf32(acc[nt][0], acc[nt][1], acc[nt][2], acc[nt][3],
                         a0h, a1h, a2h, a3h, b0h, b1h);
                mma_tf32(acc[nt][0], acc[nt][1], acc[nt][2], acc[nt][3],
                         a0h, a1h, a2h, a3h, b0l, b1l);
                mma_tf32(acc[nt][0], acc[nt][1], acc[nt][2], acc[nt][3],
                         a0l, a1l, a2l, a3l, b0h, b1h);
            }
        }
        // epilogue: D fragment -> sh1 with bias+relu
#pragma unroll
        for (int nt = 0; nt < 4; nt++) {
            const int col = w * 32 + nt * 8 + 2 * tig;
            const float b0 = fc_b[col], b1 = fc_b[col + 1];
            sh1[g * 128 + col]           = fmaxf(acc[nt][0] + b0, 0.f);
            sh1[g * 128 + col + 1]       = fmaxf(acc[nt][1] + b1, 0.f);
            sh1[(g + 8) * 128 + col]     = fmaxf(acc[nt][2] + b0, 0.f);
            sh1[(g + 8) * 128 + col + 1] = fmaxf(acc[nt][3] + b1, 0.f);
        }
    }
    __syncthreads();

    // ---- stage 2: h2[r][c] = h1[r] . W2[:,c] + fc2_b[c] ----
    {
        const int c = t & 63;
        const int rbase = (t >> 6) * 8;
        float acc[8];
#pragma unroll
        for (int r = 0; r < 8; r++) acc[r] = 0.f;
        const float4* wp = (const float4*)g_w2T + c;   // [k4][64] float4
#pragma unroll 4
        for (int k4 = 0; k4 < 32; k4++) {
            const float4 w4 = wp[k4 * 64];
#pragma unroll
            for (int r = 0; r < 8; r++) {
                const float4 h4 = ((const float4*)sh1)[(rbase + r) * 32 + k4];
                acc[r] = fmaf(h4.x, w4.x, acc[r]);
                acc[r] = fmaf(h4.y, w4.y, acc[r]);
                acc[r] = fmaf(h4.z, w4.z, acc[r]);
                acc[r] = fmaf(h4.w, w4.w, acc[r]);
            }
        }
        const float bb = fc2_b[c];
#pragma unroll
        for (int r = 0; r < 8; r++)
            sh2[(rbase + r) * 64 + c] = acc[r] + bb;
    }
    __syncthreads();

    // ---- stage 3 ----
    for (int idx = t; idx < 160; idx += 128) {
        const int r = idx / 10, c = idx - r * 10;
        float a = sb3[c];
        const float* h = sh2 + r * 64;
        const float* wv = sw3 + c * 64;
#pragma unroll
        for (int k = 0; k < 64; k++) a = fmaf(h[k], wv[k], a);
        out[(r0 + r) * 10 + c] = a;
    }
}

// ---------------------------------------------------------------------------
extern "C" void kernel_launch(void* const* d_in, const int* in_sizes, int n_in,
                              void* d_out, int out_size) {
    const float* x       = (const float*)d_in[0];
    const float* conv1_w = (const float*)d_in[1];
    const float* conv1_b = (const float*)d_in[2];
    const float* conv2_w = (const float*)d_in[3];
    const float* conv2_b = (const float*)d_in[4];
    const float* fc_w    = (const float*)d_in[5];
    const float* fc_b    = (const float*)d_in[6];
    const float* fc2_w   = (const float*)d_in[7];
    const float* fc2_b   = (const float*)d_in[8];
    const float* fc3_w   = (const float*)d_in[9];
    const float* fc3_b   = (const float*)d_in[10];
    float* out = (float*)d_out;

    const int B = in_sizes[0] / 784;

    kT<<<200, 256>>>(fc_w, fc2_w);
    k12_conv<<<B / 2, 160>>>(x, conv1_w, conv1_b, conv2_w, conv2_b);
    k3_fc<<<B / 16, 128>>>(fc_b, fc2_b, fc3_w, fc3_b, out);
}

// round 14
// speedup vs baseline: 1.0438x; 1.0438x over previous
#include <cuda_runtime.h>

#define BMAX 16384

__device__ float g_y2[BMAX * 400];      // conv2+pool output, flattened (C,H,W)
__device__ float g_w1T[104 * 512];      // fc_w packed [k/4][c][4], padded 100->104 k4-rows
__device__ float g_w2T[128 * 64];       // fc2_w packed [k/4][c][4]

__device__ __forceinline__ float4 fma4(float4 a, float4 b, float4 c) {
    return make_float4(fmaf(a.x, b.x, c.x), fmaf(a.y, b.y, c.y),
                       fmaf(a.z, b.z, c.z), fmaf(a.w, b.w, c.w));
}

// ---------------------------------------------------------------------------
// Weight repack: w1T[(k/4)][c][4] so k3 loads 4 k-weights per LDG.128.
// ---------------------------------------------------------------------------
__global__ void __launch_bounds__(256) kT(const float* __restrict__ fc_w,
                                          const float* __restrict__ fc2_w) {
    const int i = blockIdx.x * 256 + threadIdx.x;
    if (i < 51200) {
        const int c = i / 400, k = i - c * 400;
        g_w1T[(k >> 2) * 512 + c * 4 + (k & 3)] = fc_w[i];
    }
    if (i < 8192) {
        const int c = i / 128, k = i - c * 128;
        g_w2T[(k >> 2) * 256 + c * 4 + (k & 3)] = fc2_w[i];
    }
}

// ---------------------------------------------------------------------------
// Fused conv kernel, 2 images / 192 threads (R7 structure, wider block).
// ---------------------------------------------------------------------------
__global__ void __launch_bounds__(192) k12_conv(const float* __restrict__ x,
                                                const float* __restrict__ w1,
                                                const float* __restrict__ b1,
                                                const float* __restrict__ w2,
                                                const float* __restrict__ b2) {
    __shared__ __align__(16) float SM[8888];
    float*  Tbuf = SM;                   // [2 img][12 y][8 ic][5 p][4] = 3840
    float*  sx   = SM;                   // [2 img][784] (alias, disjoint lifetime)
    float*  sy1  = SM + 3840;            // [2 img][8 ic][13 y][16] = 3328
    float4* suw4 = (float4*)(SM + 7168); // [16 oc][25] float4
    float4* sw14 = (float4*)(SM + 8768); // [8 oc][3 ky] float4 (w0,w1,w2,0)
    float*  sb1  = SM + 8864;
    float*  sb2  = SM + 8872;

    const int img0 = blockIdx.x * 2;
    const int t = threadIdx.x;

    // ---- stage 0 ----
    if (t < 24) {
        const int oc = t / 3, ky = t - oc * 3;
        const float* g = w1 + oc * 9 + ky * 3;
        sw14[t] = make_float4(g[0], g[1], g[2], 0.f);
    }
    if (t >= 80 && t < 88)   sb1[t - 80] = b1[t - 80];
    if (t >= 88 && t < 104)  sb2[t - 88] = b2[t - 88];
    for (int i = t; i < 384; i += 192) {         // Winograd weight transform
        const int oc = i / 24, rem = i - oc * 24;
        const int ic = rem / 3, ky = rem - ic * 3;
        const float* g = w2 + oc * 72 + ic * 9 + ky * 3;
        const float a = g[0], bq = g[1], c = g[2];
        suw4[oc * 25 + ic * 3 + ky] =
            make_float4(a, 0.5f * (a + bq + c), 0.5f * (a - bq + c), c);
    }
    {
        const float4* xs = (const float4*)(x + img0 * 784);
        for (int i = t; i < 392; i += 192) ((float4*)sx)[i] = xs[i];
    }
    __syncthreads();

    // ---- phase A: conv1 + bias + relu + pool -> sy1 ----
    for (int i = t; i < 338; i += 192) {
        const int sub = i / 169;
        const int local = i - sub * 169;
        const int py = local / 13, px = local - py * 13;
        const float* xim = sx + sub * 784 + (2 * py) * 28 + 2 * px;

        float win[4][4];
#pragma unroll
        for (int j = 0; j < 4; j++) {
            const float2* rr = (const float2*)(xim + j * 28);
            const float2 a = rr[0], b = rr[1];
            win[j][0] = a.x; win[j][1] = a.y; win[j][2] = b.x; win[j][3] = b.y;
        }

        float* outp = sy1 + sub * 1664 + py * 16 + px;
#pragma unroll
        for (int oc = 0; oc < 8; oc++) {
            float c00 = 0.f, c01 = 0.f, c10 = 0.f, c11 = 0.f;
#pragma unroll
            for (int ky = 0; ky < 3; ky++) {
                const float4 wv = sw14[oc * 3 + ky];
                c00 = fmaf(win[ky][0], wv.x, c00);
                c00 = fmaf(win[ky][1], wv.y, c00);
                c00 = fmaf(win[ky][2], wv.z, c00);
                c01 = fmaf(win[ky][1], wv.x, c01);
                c01 = fmaf(win[ky][2], wv.y, c01);
                c01 = fmaf(win[ky][3], wv.z, c01);
                c10 = fmaf(win[ky + 1][0], wv.x, c10);
                c10 = fmaf(win[ky + 1][1], wv.y, c10);
                c10 = fmaf(win[ky + 1][2], wv.z, c10);
                c11 = fmaf(win[ky + 1][1], wv.x, c11);
                c11 = fmaf(win[ky + 1][2], wv.y, c11);
                c11 = fmaf(win[ky + 1][3], wv.z, c11);
            }
            const float m = fmaxf(fmaxf(c00, c01), fmaxf(c10, c11)) + sb1[oc];
            outp[oc * 208] = fmaxf(m, 0.f);
        }
    }
    __syncthreads();

    // ---- phase B1: input transform (exactly 192 items = 1 iteration) ----
    {
        const int i = t;
        const int img = i / 96, rem = i - img * 96;
        const int y = rem / 8, ic = rem - y * 8;
        const float4* rp = (const float4*)(sy1 + img * 1664 + ic * 208 + y * 16);
        float r[12];
#pragma unroll
        for (int m = 0; m < 3; m++) {
            const float4 v = rp[m];
            r[4 * m] = v.x; r[4 * m + 1] = v.y; r[4 * m + 2] = v.z; r[4 * m + 3] = v.w;
        }
        float4* dst = (float4*)(Tbuf + img * 1920 + (y * 8 + ic) * 20);
#pragma unroll
        for (int p = 0; p < 5; p++)
            dst[p] = make_float4(r[2 * p] - r[2 * p + 2],
                                 r[2 * p + 1] + r[2 * p + 2],
                                 r[2 * p + 2] - r[2 * p + 1],
                                 r[2 * p + 1] - r[2 * p + 3]);
    }
    __syncthreads();

    // ---- phase B2: m-space conv2 + pool + bias + relu (160 active) ----
    if (t < 160) {
        const int sub = t / 80;
        const int r = t - sub * 80;
        const int py = r >> 4, oc = r & 15;
        const float* Timg = Tbuf + sub * 1920;
        const float4* wbase = suw4 + oc * 25;

        float4 macc[2][5];
#pragma unroll
        for (int a = 0; a < 2; a++)
#pragma unroll
            for (int p = 0; p < 5; p++) macc[a][p] = make_float4(0.f, 0.f, 0.f, 0.f);

#pragma unroll 2
        for (int ic = 0; ic < 8; ic++) {
            const float4 u0 = wbase[ic * 3 + 0];
            const float4 u1 = wbase[ic * 3 + 1];
            const float4 u2 = wbase[ic * 3 + 2];
#pragma unroll
            for (int s = 0; s < 4; s++) {
                const float4* Trow = (const float4*)(Timg + ((2 * py + s) * 8 + ic) * 20);
                float4 tr[5];
#pragma unroll
                for (int p = 0; p < 5; p++) tr[p] = Trow[p];
                if (s < 3) {
                    const float4 u = (s == 0) ? u0 : (s == 1) ? u1 : u2;
#pragma unroll
                    for (int p = 0; p < 5; p++) macc[0][p] = fma4(tr[p], u, macc[0][p]);
                }
                if (s >= 1) {
                    const float4 u = (s == 1) ? u0 : (s == 2) ? u1 : u2;
#pragma unroll
                    for (int p = 0; p < 5; p++) macc[1][p] = fma4(tr[p], u, macc[1][p]);
                }
            }
        }

        float* outp = g_y2 + (img0 + sub) * 400 + oc * 25 + py * 5;
        const float bb = sb2[oc];
#pragma unroll
        for (int p = 0; p < 5; p++) {
            const float o00 = macc[0][p].x + macc[0][p].y + macc[0][p].z;
            const float o01 = macc[0][p].y - macc[0][p].z - macc[0][p].w;
            const float o10 = macc[1][p].x + macc[1][p].y + macc[1][p].z;
            const float o11 = macc[1][p].y - macc[1][p].z - macc[1][p].w;
            const float m = fmaxf(fmaxf(o00, o01), fmaxf(o10, o11));
            outp[p] = fmaxf(m + bb, 0.f);
        }
    }
}

// ---------------------------------------------------------------------------
// Kernel 3: fc1+relu, fc2, fc3. 16 rows/block, 128 threads.
// Stage-1 weight LDGs prefetched 4 deep via NAMED registers, branch-free
// (w1T padded so tail prefetches stay in bounds; results unused).
// ---------------------------------------------------------------------------
__global__ void __launch_bounds__(128) k3_fc(const float* __restrict__ fc_b,
                                             const float* __restrict__ fc2_b,
                                             const float* __restrict__ fc3_w,
                                             const float* __restrict__ fc3_b,
                                             float* __restrict__ out) {
    __shared__ __align__(16) float sx[16 * 400];
    __shared__ __align__(16) float sh1[16 * 128];
    __shared__ __align__(16) float sh2[16 * 64];
    __shared__ __align__(16) float sw3[640];
    __shared__ float sb3[10];

    const int r0 = blockIdx.x * 16;
    const int t = threadIdx.x;

    {
        const float4* xin = (const float4*)(g_y2 + r0 * 400);
        for (int i = t; i < 1600; i += 128) ((float4*)sx)[i] = xin[i];
        for (int i = t; i < 160; i += 128) ((float4*)sw3)[i] = ((const float4*)fc3_w)[i];
        if (t < 10) sb3[t] = fc3_b[t];
    }
    __syncthreads();

    // ---- stage 1: h1[r][t] = relu(X[r] . W1[:,t] + fc_b[t]) ----
    {
        float acc[16];
#pragma unroll
        for (int r = 0; r < 16; r++) acc[r] = 0.f;
        const float4* wp = (const float4*)g_w1T + t;   // [k4][128] float4

        float4 wa = wp[0 * 128], wb = wp[1 * 128], wc = wp[2 * 128], wd = wp[3 * 128];

        for (int k4 = 0; k4 < 100; k4 += 4) {
            // prefetch next group (pad rows 100..103 exist; tail results unused)
            const float4 na = wp[(k4 + 4) * 128];
            const float4 nb = wp[(k4 + 5) * 128];
            const float4 nc = wp[(k4 + 6) * 128];
            const float4 nd = wp[(k4 + 7) * 128];
#pragma unroll
            for (int j = 0; j < 4; j++) {
                const float4 w4 = (j == 0) ? wa : (j == 1) ? wb : (j == 2) ? wc : wd;
#pragma unroll
                for (int r = 0; r < 16; r++) {
                    const float4 x4 = ((const float4*)sx)[r * 100 + k4 + j];
                    acc[r] = fmaf(x4.x, w4.x, acc[r]);
                    acc[r] = fmaf(x4.y, w4.y, acc[r]);
                    acc[r] = fmaf(x4.z, w4.z, acc[r]);
                    acc[r] = fmaf(x4.w, w4.w, acc[r]);
                }
            }
            wa = na; wb = nb; wc = nc; wd = nd;
        }
        const float bb = fc_b[t];
#pragma unroll
        for (int r = 0; r < 16; r++)
            sh1[r * 128 + t] = fmaxf(acc[r] + bb, 0.f);
    }
    __syncthreads();

    // ---- stage 2: h2[r][c] = h1[r] . W2[:,c] + fc2_b[c] ----
    {
        const int c = t & 63;
        const int rbase = (t >> 6) * 8;
        float acc[8];
#pragma unroll
        for (int r = 0; r < 8; r++) acc[r] = 0.f;
        const float4* wp = (const float4*)g_w2T + c;   // [k4][64] float4
#pragma unroll 4
        for (int k4 = 0; k4 < 32; k4++) {
            const float4 w4 = wp[k4 * 64];
#pragma unroll
            for (int r = 0; r < 8; r++) {
                const float4 h4 = ((const float4*)sh1)[(rbase + r) * 32 + k4];
                acc[r] = fmaf(h4.x, w4.x, acc[r]);
                acc[r] = fmaf(h4.y, w4.y, acc[r]);
                acc[r] = fmaf(h4.z, w4.z, acc[r]);
                acc[r] = fmaf(h4.w, w4.w, acc[r]);
            }
        }
        const float bb = fc2_b[c];
#pragma unroll
        for (int r = 0; r < 8; r++)
            sh2[(rbase + r) * 64 + c] = acc[r] + bb;
    }
    __syncthreads();

    // ---- stage 3 ----
    for (int idx = t; idx < 160; idx += 128) {
        const int r = idx / 10, c = idx - r * 10;
        float a = sb3[c];
        const float* h = sh2 + r * 64;
        const float* wv = sw3 + c * 64;
#pragma unroll
        for (int k = 0; k < 64; k++) a = fmaf(h[k], wv[k], a);
        out[(r0 + r) * 10 + c] = a;
    }
}

// ---------------------------------------------------------------------------
extern "C" void kernel_launch(void* const* d_in, const int* in_sizes, int n_in,
                              void* d_out, int out_size) {
    const float* x       = (const float*)d_in[0];
    const float* conv1_w = (const float*)d_in[1];
    const float* conv1_b = (const float*)d_in[2];
    const float* conv2_w = (const float*)d_in[3];
    const float* conv2_b = (const float*)d_in[4];
    const float* fc_w    = (const float*)d_in[5];
    const float* fc_b    = (const float*)d_in[6];
    const float* fc2_w   = (const float*)d_in[7];
    const float* fc2_b   = (const float*)d_in[8];
    const float* fc3_w   = (const float*)d_in[9];
    const float* fc3_b   = (const float*)d_in[10];
    float* out = (float*)d_out;

    const int B = in_sizes[0] / 784;

    kT<<<200, 256>>>(fc_w, fc2_w);
    k12_conv<<<B / 2, 192>>>(x, conv1_w, conv1_b, conv2_w, conv2_b);
    k3_fc<<<B / 16, 128>>>(fc_b, fc2_b, fc3_w, fc3_b, out);
}